// round 5
// baseline (speedup 1.0000x reference)
#include <cuda_runtime.h>
#include <cuda_bf16.h>
#include <math.h>

// Inputs (metadata order): Xemb [8192,128] f32, scores f32 (unused),
// h_bias scalar f32, labels i32 (unused), pos_idx [P,2] i32, neg_idx [P,2] i32.
// Output: 2 floats {pos_loss, neg_loss}.

#define NUM_BLOCKS 444    // 148 SMs * 3 (one wave at occ=3)
#define THREADS    256    // 8 warps/block

__device__ float2 g_partials[NUM_BLOCKS];
__device__ unsigned int g_done_count = 0;

// 8 lanes per pair: lane loads 4 float4 from each row (8 LDG.128 in flight).
__device__ __forceinline__ float pair_partial8(const float* __restrict__ X,
                                               int2 idx, int sub)
{
    const float4* ra = (const float4*)(X + (size_t)idx.x * 128);
    const float4* rb = (const float4*)(X + (size_t)idx.y * 128);
    float4 a0 = __ldg(ra + sub);       float4 a1 = __ldg(ra + sub + 8);
    float4 a2 = __ldg(ra + sub + 16);  float4 a3 = __ldg(ra + sub + 24);
    float4 b0 = __ldg(rb + sub);       float4 b1 = __ldg(rb + sub + 8);
    float4 b2 = __ldg(rb + sub + 16);  float4 b3 = __ldg(rb + sub + 24);

    float s = 0.f, d;
    d = a0.x - b0.x; s += d * d;  d = a0.y - b0.y; s += d * d;
    d = a0.z - b0.z; s += d * d;  d = a0.w - b0.w; s += d * d;
    d = a1.x - b1.x; s += d * d;  d = a1.y - b1.y; s += d * d;
    d = a1.z - b1.z; s += d * d;  d = a1.w - b1.w; s += d * d;
    d = a2.x - b2.x; s += d * d;  d = a2.y - b2.y; s += d * d;
    d = a2.z - b2.z; s += d * d;  d = a2.w - b2.w; s += d * d;
    d = a3.x - b3.x; s += d * d;  d = a3.y - b3.y; s += d * d;
    d = a3.z - b3.z; s += d * d;  d = a3.w - b3.w; s += d * d;
    return s;
}

__global__ __launch_bounds__(THREADS, 3)
void pair_loss_fused_kernel(const float* __restrict__ X,
                            const float* __restrict__ h_bias,
                            const int2* __restrict__ pos_idx,
                            const int2* __restrict__ neg_idx,
                            int P,
                            float* __restrict__ out)
{
    const int lane  = threadIdx.x & 31;
    const int warp  = threadIdx.x >> 5;
    const int grp   = lane >> 3;       // 0..3: pair within the warp
    const int sub   = lane & 7;        // 0..7: lane within the pair group
    const int gwarp = (blockIdx.x * blockDim.x + threadIdx.x) >> 5;
    const int G     = ((NUM_BLOCKS * THREADS) >> 5) * 4;   // total groups
    const long g0   = (long)gwarp * 4;
    const long ggrp = g0 + grp;

    const float bias = log1pf(expf(*h_bias));  // softplus

    float pos_acc = 0.0f;   // per-lane partials: no per-pair reduce for pos
    float neg_acc = 0.0f;

    // ---- positive pairs, 2 pairs per group per iteration ----
    {
        const long nIter = (P > g0) ? ((P - 1 - g0) / G + 1) : 0;
        long t = ggrp;
        for (long k = 0; k < nIter; k += 2, t += 2L * G) {
            const long t2 = t + G;
            const int2 i1 = (t  < P) ? __ldg(&pos_idx[t])  : make_int2(0, 0);
            const int2 i2 = (t2 < P && k + 1 < nIter) ? __ldg(&pos_idx[t2]) : make_int2(0, 0);
            // invalid -> rows identical -> contributes exactly 0
            pos_acc += pair_partial8(X, i1, sub);
            pos_acc += pair_partial8(X, i2, sub);
        }
    }

    // ---- negative pairs, 2 pairs per group per iteration ----
    {
        const long nIter = (P > g0) ? ((P - 1 - g0) / G + 1) : 0;
        long t = ggrp;
        for (long k = 0; k < nIter; k += 2, t += 2L * G) {
            const long t2 = t + G;
            const bool v1 = (t  < P);
            const bool v2 = (t2 < P) && (k + 1 < nIter);
            const int2 i1 = v1 ? __ldg(&neg_idx[t])  : make_int2(0, 0);
            const int2 i2 = v2 ? __ldg(&neg_idx[t2]) : make_int2(0, 0);

            float s1 = pair_partial8(X, i1, sub);
            float s2 = pair_partial8(X, i2, sub);

            s1 += __shfl_xor_sync(0xFFFFFFFFu, s1, 1);
            s2 += __shfl_xor_sync(0xFFFFFFFFu, s2, 1);
            s1 += __shfl_xor_sync(0xFFFFFFFFu, s1, 2);
            s2 += __shfl_xor_sync(0xFFFFFFFFu, s2, 2);
            s1 += __shfl_xor_sync(0xFFFFFFFFu, s1, 4);
            s2 += __shfl_xor_sync(0xFFFFFFFFu, s2, 4);

            const float d1 = sqrtf(s1);
            const float d2 = sqrtf(s2);
            const float r1 = fmaxf(bias - d1, 0.0f);
            const float r2 = fmaxf(bias - d2, 0.0f);
            neg_acc += (v1 && sub == 0) ? r1 * r1 : 0.0f;
            neg_acc += (v2 && sub == 0) ? r2 * r2 : 0.0f;
        }
    }

    // ---- block reduce ----
    __shared__ float s_pos[THREADS / 32];
    __shared__ float s_neg[THREADS / 32];
    float p = pos_acc, n = neg_acc;
    #pragma unroll
    for (int o = 16; o > 0; o >>= 1) {
        p += __shfl_xor_sync(0xFFFFFFFFu, p, o);
        n += __shfl_xor_sync(0xFFFFFFFFu, n, o);
    }
    if (lane == 0) { s_pos[warp] = p; s_neg[warp] = n; }
    __syncthreads();

    __shared__ bool s_is_last;
    if (warp == 0) {
        float pp = (lane < THREADS / 32) ? s_pos[lane] : 0.0f;
        float nn = (lane < THREADS / 32) ? s_neg[lane] : 0.0f;
        #pragma unroll
        for (int o = 4; o > 0; o >>= 1) {
            pp += __shfl_xor_sync(0xFFFFFFFFu, pp, o);
            nn += __shfl_xor_sync(0xFFFFFFFFu, nn, o);
        }
        if (lane == 0) {
            g_partials[blockIdx.x] = make_float2(pp, nn);
            __threadfence();
            unsigned int prev = atomicAdd(&g_done_count, 1u);
            s_is_last = (prev == (unsigned int)(gridDim.x - 1));
        }
    }
    __syncthreads();

    // ---- last block: final deterministic reduction in double ----
    if (s_is_last) {
        double ps = 0.0, ns = 0.0;
        for (int i = threadIdx.x; i < NUM_BLOCKS; i += THREADS) {
            float2 v = g_partials[i];
            ps += (double)v.x;
            ns += (double)v.y;
        }
        #pragma unroll
        for (int o = 16; o > 0; o >>= 1) {
            ps += __shfl_xor_sync(0xFFFFFFFFu, ps, o);
            ns += __shfl_xor_sync(0xFFFFFFFFu, ns, o);
        }
        __shared__ double sp[THREADS / 32], sn[THREADS / 32];
        if (lane == 0) { sp[warp] = ps; sn[warp] = ns; }
        __syncthreads();
        if (threadIdx.x == 0) {
            double tp = 0.0, tn = 0.0;
            for (int w = 0; w < THREADS / 32; w++) { tp += sp[w]; tn += sn[w]; }
            out[0] = (float)(0.5 * tp / (double)P);
            out[1] = (float)(0.5 * tn / (double)P);
            g_done_count = 0;   // reset for next graph replay
        }
    }
}

extern "C" void kernel_launch(void* const* d_in, const int* in_sizes, int n_in,
                              void* d_out, int out_size)
{
    const float* X      = (const float*)d_in[0];
    const float* h_bias = (const float*)d_in[2];
    const int2*  pos    = (const int2*)d_in[4];
    const int2*  neg    = (const int2*)d_in[5];
    const int P = in_sizes[4] / 2;

    pair_loss_fused_kernel<<<NUM_BLOCKS, THREADS>>>(X, h_bias, pos, neg, P, (float*)d_out);
}

// round 6
// speedup vs baseline: 1.0651x; 1.0651x over previous
#include <cuda_runtime.h>
#include <cuda_fp16.h>
#include <math.h>

// Inputs (metadata order): Xemb [8192,128] f32, scores f32 (unused),
// h_bias scalar f32, labels i32 (unused), pos_idx [P,2] i32, neg_idx [P,2] i32.
// Output: 2 floats {pos_loss, neg_loss}.

#define N_ROWS     8192
#define NUM_BLOCKS 592    // 148 SMs * 4
#define THREADS    256    // 8 warps/block

__device__ __half2 g_Xh[N_ROWS * 64];   // fp16-staged Xemb (2 MB)
__device__ float2 g_partials[NUM_BLOCKS];
__device__ unsigned int g_done_count = 0;

__global__ void convert_kernel(const float* __restrict__ X)
{
    const int t = blockIdx.x * blockDim.x + threadIdx.x;   // over 8192*64 half2
    if (t < N_ROWS * 64) {
        float2 v = ((const float2*)X)[t];
        g_Xh[t] = __float22half2_rn(v);
    }
}

// Accumulate squared diffs of 8 halves (one uint4 from each row), fp32 math.
__device__ __forceinline__ void acc8(uint4 a, uint4 b, float& s)
{
    const __half2* ah = (const __half2*)&a;
    const __half2* bh = (const __half2*)&b;
    #pragma unroll
    for (int j = 0; j < 4; j++) {
        float2 fa = __half22float2(ah[j]);
        float2 fb = __half22float2(bh[j]);
        float dx = fa.x - fb.x;
        float dy = fa.y - fb.y;
        s += dx * dx + dy * dy;
    }
}

__global__ __launch_bounds__(THREADS, 4)
void pair_loss_fused_kernel(const float* __restrict__ h_bias,
                            const int2* __restrict__ pos_idx,
                            const int2* __restrict__ neg_idx,
                            int P,
                            float* __restrict__ out)
{
    const int lane  = threadIdx.x & 31;
    const int warp  = threadIdx.x >> 5;
    const int grp   = lane >> 3;       // 0..3: pair within the warp
    const int sub   = lane & 7;        // 0..7: lane within the pair group
    const int gwarp = (blockIdx.x * blockDim.x + threadIdx.x) >> 5;
    const int G     = ((NUM_BLOCKS * THREADS) >> 5) * 4;   // total groups
    const long g0   = (long)gwarp * 4;
    const long ggrp = g0 + grp;

    const float bias = log1pf(expf(*h_bias));  // softplus

    float pos_acc = 0.0f;   // per-lane partials: no per-pair reduce for pos
    float neg_acc = 0.0f;

    // Row = 128 halves = 256B = 16 uint4. 8 lanes/pair: lane loads uint4 at
    // sub and sub+8 from each row -> 4 LDG.128 per pair, 8 in flight w/ unroll2.
    const uint4* Xh = (const uint4*)g_Xh;

    // ---- positive pairs (2 per group-iteration, front-batched loads) ----
    {
        const long nIter = (P > g0) ? ((P - 1 - g0) / G + 1) : 0;
        long t = ggrp;
        for (long k = 0; k < nIter; k += 2, t += 2L * G) {
            const long t2 = t + G;
            const int2 i1 = (t  < P) ? __ldg(&pos_idx[t])  : make_int2(0, 0);
            const int2 i2 = (t2 < P && k + 1 < nIter) ? __ldg(&pos_idx[t2]) : make_int2(0, 0);

            const uint4* ra1 = Xh + (size_t)i1.x * 16;
            const uint4* rb1 = Xh + (size_t)i1.y * 16;
            const uint4* ra2 = Xh + (size_t)i2.x * 16;
            const uint4* rb2 = Xh + (size_t)i2.y * 16;
            uint4 a10 = __ldg(ra1 + sub); uint4 a11 = __ldg(ra1 + sub + 8);
            uint4 b10 = __ldg(rb1 + sub); uint4 b11 = __ldg(rb1 + sub + 8);
            uint4 a20 = __ldg(ra2 + sub); uint4 a21 = __ldg(ra2 + sub + 8);
            uint4 b20 = __ldg(rb2 + sub); uint4 b21 = __ldg(rb2 + sub + 8);

            // invalid -> rows identical -> contributes exactly 0
            acc8(a10, b10, pos_acc); acc8(a11, b11, pos_acc);
            acc8(a20, b20, pos_acc); acc8(a21, b21, pos_acc);
        }
    }

    // ---- negative pairs ----
    {
        const long nIter = (P > g0) ? ((P - 1 - g0) / G + 1) : 0;
        long t = ggrp;
        for (long k = 0; k < nIter; k += 2, t += 2L * G) {
            const long t2 = t + G;
            const bool v1 = (t  < P);
            const bool v2 = (t2 < P) && (k + 1 < nIter);
            const int2 i1 = v1 ? __ldg(&neg_idx[t])  : make_int2(0, 0);
            const int2 i2 = v2 ? __ldg(&neg_idx[t2]) : make_int2(0, 0);

            const uint4* ra1 = Xh + (size_t)i1.x * 16;
            const uint4* rb1 = Xh + (size_t)i1.y * 16;
            const uint4* ra2 = Xh + (size_t)i2.x * 16;
            const uint4* rb2 = Xh + (size_t)i2.y * 16;
            uint4 a10 = __ldg(ra1 + sub); uint4 a11 = __ldg(ra1 + sub + 8);
            uint4 b10 = __ldg(rb1 + sub); uint4 b11 = __ldg(rb1 + sub + 8);
            uint4 a20 = __ldg(ra2 + sub); uint4 a21 = __ldg(ra2 + sub + 8);
            uint4 b20 = __ldg(rb2 + sub); uint4 b21 = __ldg(rb2 + sub + 8);

            float s1 = 0.f, s2 = 0.f;
            acc8(a10, b10, s1); acc8(a11, b11, s1);
            acc8(a20, b20, s2); acc8(a21, b21, s2);

            s1 += __shfl_xor_sync(0xFFFFFFFFu, s1, 1);
            s2 += __shfl_xor_sync(0xFFFFFFFFu, s2, 1);
            s1 += __shfl_xor_sync(0xFFFFFFFFu, s1, 2);
            s2 += __shfl_xor_sync(0xFFFFFFFFu, s2, 2);
            s1 += __shfl_xor_sync(0xFFFFFFFFu, s1, 4);
            s2 += __shfl_xor_sync(0xFFFFFFFFu, s2, 4);

            const float d1 = sqrtf(s1);
            const float d2 = sqrtf(s2);
            const float r1 = fmaxf(bias - d1, 0.0f);
            const float r2 = fmaxf(bias - d2, 0.0f);
            neg_acc += (v1 && sub == 0) ? r1 * r1 : 0.0f;
            neg_acc += (v2 && sub == 0) ? r2 * r2 : 0.0f;
        }
    }

    // ---- block reduce ----
    __shared__ float s_pos[THREADS / 32];
    __shared__ float s_neg[THREADS / 32];
    float p = pos_acc, n = neg_acc;
    #pragma unroll
    for (int o = 16; o > 0; o >>= 1) {
        p += __shfl_xor_sync(0xFFFFFFFFu, p, o);
        n += __shfl_xor_sync(0xFFFFFFFFu, n, o);
    }
    if (lane == 0) { s_pos[warp] = p; s_neg[warp] = n; }
    __syncthreads();

    __shared__ bool s_is_last;
    if (warp == 0) {
        float pp = (lane < THREADS / 32) ? s_pos[lane] : 0.0f;
        float nn = (lane < THREADS / 32) ? s_neg[lane] : 0.0f;
        #pragma unroll
        for (int o = 4; o > 0; o >>= 1) {
            pp += __shfl_xor_sync(0xFFFFFFFFu, pp, o);
            nn += __shfl_xor_sync(0xFFFFFFFFu, nn, o);
        }
        if (lane == 0) {
            g_partials[blockIdx.x] = make_float2(pp, nn);
            __threadfence();
            unsigned int prev = atomicAdd(&g_done_count, 1u);
            s_is_last = (prev == (unsigned int)(gridDim.x - 1));
        }
    }
    __syncthreads();

    // ---- last block: final deterministic reduction in double ----
    if (s_is_last) {
        double ps = 0.0, ns = 0.0;
        for (int i = threadIdx.x; i < NUM_BLOCKS; i += THREADS) {
            float2 v = g_partials[i];
            ps += (double)v.x;
            ns += (double)v.y;
        }
        #pragma unroll
        for (int o = 16; o > 0; o >>= 1) {
            ps += __shfl_xor_sync(0xFFFFFFFFu, ps, o);
            ns += __shfl_xor_sync(0xFFFFFFFFu, ns, o);
        }
        __shared__ double sp[THREADS / 32], sn[THREADS / 32];
        if (lane == 0) { sp[warp] = ps; sn[warp] = ns; }
        __syncthreads();
        if (threadIdx.x == 0) {
            double tp = 0.0, tn = 0.0;
            for (int w = 0; w < THREADS / 32; w++) { tp += sp[w]; tn += sn[w]; }
            out[0] = (float)(0.5 * tp / (double)P);
            out[1] = (float)(0.5 * tn / (double)P);
            g_done_count = 0;   // reset for next graph replay
        }
    }
}

extern "C" void kernel_launch(void* const* d_in, const int* in_sizes, int n_in,
                              void* d_out, int out_size)
{
    const float* X      = (const float*)d_in[0];
    const float* h_bias = (const float*)d_in[2];
    const int2*  pos    = (const int2*)d_in[4];
    const int2*  neg    = (const int2*)d_in[5];
    const int P = in_sizes[4] / 2;

    convert_kernel<<<(N_ROWS * 64 + 255) / 256, 256>>>(X);
    pair_loss_fused_kernel<<<NUM_BLOCKS, THREADS>>>(h_bias, pos, neg, P, (float*)d_out);
}

// round 7
// speedup vs baseline: 1.3220x; 1.2412x over previous
#include <cuda_runtime.h>
#include <cuda_fp16.h>
#include <math.h>

// Inputs (metadata order): Xemb [8192,128] f32, scores f32 (unused),
// h_bias scalar f32, labels i32 (unused), pos_idx [P,2] i32, neg_idx [P,2] i32.
// Output: 2 floats {pos_loss, neg_loss}.

#define N_ROWS     8192
#define NUM_BLOCKS 592    // 148 SMs * 4
#define THREADS    256    // 8 warps/block

__device__ __half2 g_Xh[N_ROWS * 64];   // fp16-staged Xemb (2 MB)
__device__ float2 g_partials[NUM_BLOCKS];
__device__ unsigned int g_done_count = 0;

__global__ void convert_kernel(const float* __restrict__ X)
{
    // 8192 rows * 512B = 4MB input; each thread converts 4 floats -> 4 halves.
    const int t = blockIdx.x * blockDim.x + threadIdx.x;   // over 8192*32
    if (t < N_ROWS * 32) {
        float4 v = ((const float4*)X)[t];
        __half2 h0 = __floats2half2_rn(v.x, v.y);
        __half2 h1 = __floats2half2_rn(v.z, v.w);
        g_Xh[t * 2]     = h0;
        g_Xh[t * 2 + 1] = h1;
    }
}

// Accumulate (a-b)^2 for 8 halves in packed fp16: 2 instr per half2.
__device__ __forceinline__ void acc8h(uint4 a, uint4 b, __half2& acc)
{
    const __half2* ah = (const __half2*)&a;
    const __half2* bh = (const __half2*)&b;
    #pragma unroll
    for (int j = 0; j < 4; j++) {
        __half2 d = __hsub2(ah[j], bh[j]);
        acc = __hfma2(d, d, acc);
    }
}

__global__ __launch_bounds__(THREADS, 4)
void pair_loss_fused_kernel(const float* __restrict__ h_bias,
                            const int2* __restrict__ pos_idx,
                            const int2* __restrict__ neg_idx,
                            int P,
                            float* __restrict__ out)
{
    const int lane  = threadIdx.x & 31;
    const int warp  = threadIdx.x >> 5;
    const int grp   = lane >> 3;       // 0..3: pair within the warp
    const int sub   = lane & 7;        // 0..7: lane within the pair group
    const int gwarp = (blockIdx.x * blockDim.x + threadIdx.x) >> 5;
    const int G     = ((NUM_BLOCKS * THREADS) >> 5) * 4;   // total groups
    const long g0   = (long)gwarp * 4;
    const long ggrp = g0 + grp;

    const float bias = log1pf(expf(*h_bias));  // softplus

    float pos_acc = 0.0f;   // per-lane partials: no per-pair reduce for pos
    float neg_acc = 0.0f;

    // Row = 128 halves = 256B = 16 uint4. 8 lanes/pair: lane loads uint4 at
    // sub and sub+8 from each row -> 4 LDG.128 per pair, 8 in flight w/ unroll2.
    const uint4* Xh = (const uint4*)g_Xh;

    // ---- positive pairs (2 per group-iteration, front-batched loads) ----
    {
        const long nIter = (P > g0) ? ((P - 1 - g0) / G + 1) : 0;
        long t = ggrp;
        for (long k = 0; k < nIter; k += 2, t += 2L * G) {
            const long t2 = t + G;
            const int2 i1 = (t  < P) ? __ldg(&pos_idx[t])  : make_int2(0, 0);
            const int2 i2 = (t2 < P && k + 1 < nIter) ? __ldg(&pos_idx[t2]) : make_int2(0, 0);

            const uint4* ra1 = Xh + (size_t)i1.x * 16;
            const uint4* rb1 = Xh + (size_t)i1.y * 16;
            const uint4* ra2 = Xh + (size_t)i2.x * 16;
            const uint4* rb2 = Xh + (size_t)i2.y * 16;
            uint4 a10 = __ldg(ra1 + sub); uint4 a11 = __ldg(ra1 + sub + 8);
            uint4 b10 = __ldg(rb1 + sub); uint4 b11 = __ldg(rb1 + sub + 8);
            uint4 a20 = __ldg(ra2 + sub); uint4 a21 = __ldg(ra2 + sub + 8);
            uint4 b20 = __ldg(rb2 + sub); uint4 b21 = __ldg(rb2 + sub + 8);

            // invalid -> rows identical -> contributes exactly 0
            __half2 acc1 = __float2half2_rn(0.f);
            __half2 acc2 = __float2half2_rn(0.f);
            acc8h(a10, b10, acc1); acc8h(a11, b11, acc1);
            acc8h(a20, b20, acc2); acc8h(a21, b21, acc2);
            pos_acc += __low2float(acc1) + __high2float(acc1);
            pos_acc += __low2float(acc2) + __high2float(acc2);
        }
    }

    // ---- negative pairs ----
    {
        const long nIter = (P > g0) ? ((P - 1 - g0) / G + 1) : 0;
        long t = ggrp;
        for (long k = 0; k < nIter; k += 2, t += 2L * G) {
            const long t2 = t + G;
            const bool v1 = (t  < P);
            const bool v2 = (t2 < P) && (k + 1 < nIter);
            const int2 i1 = v1 ? __ldg(&neg_idx[t])  : make_int2(0, 0);
            const int2 i2 = v2 ? __ldg(&neg_idx[t2]) : make_int2(0, 0);

            const uint4* ra1 = Xh + (size_t)i1.x * 16;
            const uint4* rb1 = Xh + (size_t)i1.y * 16;
            const uint4* ra2 = Xh + (size_t)i2.x * 16;
            const uint4* rb2 = Xh + (size_t)i2.y * 16;
            uint4 a10 = __ldg(ra1 + sub); uint4 a11 = __ldg(ra1 + sub + 8);
            uint4 b10 = __ldg(rb1 + sub); uint4 b11 = __ldg(rb1 + sub + 8);
            uint4 a20 = __ldg(ra2 + sub); uint4 a21 = __ldg(ra2 + sub + 8);
            uint4 b20 = __ldg(rb2 + sub); uint4 b21 = __ldg(rb2 + sub + 8);

            __half2 acc1 = __float2half2_rn(0.f);
            __half2 acc2 = __float2half2_rn(0.f);
            acc8h(a10, b10, acc1); acc8h(a11, b11, acc1);
            acc8h(a20, b20, acc2); acc8h(a21, b21, acc2);
            float s1 = __low2float(acc1) + __high2float(acc1);
            float s2 = __low2float(acc2) + __high2float(acc2);

            s1 += __shfl_xor_sync(0xFFFFFFFFu, s1, 1);
            s2 += __shfl_xor_sync(0xFFFFFFFFu, s2, 1);
            s1 += __shfl_xor_sync(0xFFFFFFFFu, s1, 2);
            s2 += __shfl_xor_sync(0xFFFFFFFFu, s2, 2);
            s1 += __shfl_xor_sync(0xFFFFFFFFu, s1, 4);
            s2 += __shfl_xor_sync(0xFFFFFFFFu, s2, 4);

            const float d1 = sqrtf(s1);
            const float d2 = sqrtf(s2);
            const float r1 = fmaxf(bias - d1, 0.0f);
            const float r2 = fmaxf(bias - d2, 0.0f);
            neg_acc += (v1 && sub == 0) ? r1 * r1 : 0.0f;
            neg_acc += (v2 && sub == 0) ? r2 * r2 : 0.0f;
        }
    }

    // ---- block reduce ----
    __shared__ float s_pos[THREADS / 32];
    __shared__ float s_neg[THREADS / 32];
    float p = pos_acc, n = neg_acc;
    #pragma unroll
    for (int o = 16; o > 0; o >>= 1) {
        p += __shfl_xor_sync(0xFFFFFFFFu, p, o);
        n += __shfl_xor_sync(0xFFFFFFFFu, n, o);
    }
    if (lane == 0) { s_pos[warp] = p; s_neg[warp] = n; }
    __syncthreads();

    __shared__ bool s_is_last;
    if (warp == 0) {
        float pp = (lane < THREADS / 32) ? s_pos[lane] : 0.0f;
        float nn = (lane < THREADS / 32) ? s_neg[lane] : 0.0f;
        #pragma unroll
        for (int o = 4; o > 0; o >>= 1) {
            pp += __shfl_xor_sync(0xFFFFFFFFu, pp, o);
            nn += __shfl_xor_sync(0xFFFFFFFFu, nn, o);
        }
        if (lane == 0) {
            g_partials[blockIdx.x] = make_float2(pp, nn);
            __threadfence();
            unsigned int prev = atomicAdd(&g_done_count, 1u);
            s_is_last = (prev == (unsigned int)(gridDim.x - 1));
        }
    }
    __syncthreads();

    // ---- last block: final deterministic reduction in double ----
    if (s_is_last) {
        double ps = 0.0, ns = 0.0;
        for (int i = threadIdx.x; i < NUM_BLOCKS; i += THREADS) {
            float2 v = g_partials[i];
            ps += (double)v.x;
            ns += (double)v.y;
        }
        #pragma unroll
        for (int o = 16; o > 0; o >>= 1) {
            ps += __shfl_xor_sync(0xFFFFFFFFu, ps, o);
            ns += __shfl_xor_sync(0xFFFFFFFFu, ns, o);
        }
        __shared__ double sp[THREADS / 32], sn[THREADS / 32];
        if (lane == 0) { sp[warp] = ps; sn[warp] = ns; }
        __syncthreads();
        if (threadIdx.x == 0) {
            double tp = 0.0, tn = 0.0;
            for (int w = 0; w < THREADS / 32; w++) { tp += sp[w]; tn += sn[w]; }
            out[0] = (float)(0.5 * tp / (double)P);
            out[1] = (float)(0.5 * tn / (double)P);
            g_done_count = 0;   // reset for next graph replay
        }
    }
}

extern "C" void kernel_launch(void* const* d_in, const int* in_sizes, int n_in,
                              void* d_out, int out_size)
{
    const float* X      = (const float*)d_in[0];
    const float* h_bias = (const float*)d_in[2];
    const int2*  pos    = (const int2*)d_in[4];
    const int2*  neg    = (const int2*)d_in[5];
    const int P = in_sizes[4] / 2;

    convert_kernel<<<(N_ROWS * 32 + 255) / 256, 256>>>(X);
    pair_loss_fused_kernel<<<NUM_BLOCKS, THREADS>>>(h_bias, pos, neg, P, (float*)d_out);
}